// round 9
// baseline (speedup 1.0000x reference)
#include <cuda_runtime.h>

#define D_MODEL 1024
#define SEQ     2048
#define BATCH   2
#define NH      16
#define DH      64
#define M_TOT   (BATCH * SEQ)   // 4096 rows

// Scratch (allocation-free rule: __device__ globals)
__device__ float g_qkv[(size_t)M_TOT * 3 * D_MODEL];   // [4096, 3072]
__device__ float g_attn[(size_t)M_TOT * D_MODEL];      // [4096, 1024]

// ---------------------------------------------------------------------------
// Packed fp32x2 helpers (sm_103a FFMA2 path — only reachable via PTX)
// ---------------------------------------------------------------------------
__device__ __forceinline__ void ffma2(unsigned long long& d,
                                      unsigned long long a,
                                      unsigned long long b) {
    asm("fma.rn.f32x2 %0, %1, %2, %3;" : "=l"(d) : "l"(a), "l"(b), "l"(d));
}
__device__ __forceinline__ unsigned long long mul2(unsigned long long a,
                                                   unsigned long long b) {
    unsigned long long r;
    asm("mul.rn.f32x2 %0, %1, %2;" : "=l"(r) : "l"(a), "l"(b));
    return r;
}
__device__ __forceinline__ unsigned long long pack2(float lo, float hi) {
    unsigned long long r;
    asm("mov.b64 %0, {%1, %2};" : "=l"(r) : "f"(lo), "f"(hi));
    return r;
}
__device__ __forceinline__ void unpack2(unsigned long long v, float& lo, float& hi) {
    asm("mov.b64 {%0, %1}, %2;" : "=f"(lo), "=f"(hi) : "l"(v));
}

// ---------------------------------------------------------------------------
// SGEMM with bias, FFMA2 version: C[M,N] = A[M,K] @ B[K,N] + bias[N]
// 128x128 tile, BK=16, 256 threads, 8x8 per-thread micro-tile.
// A is stored in smem transposed AND duplicated ({a,a} pairs) so the
// broadcast operand of fma.rn.f32x2 loads directly with zero packing MOVs.
// Global loads for the next K-slab are register-staged under the compute.
// ---------------------------------------------------------------------------
#define BM 128
#define BN 128
#define BK 16

__global__ __launch_bounds__(256) void sgemm_bias(
    const float* __restrict__ A, const float* __restrict__ B,
    const float* __restrict__ bias, float* __restrict__ C,
    int M, int N, int K)
{
    __shared__ float Asd[BK][2 * BM];   // [kk][2m] duplicated: elem m at 2m,2m+1
    __shared__ float Bs[BK][BN];        // [kk][n] natural

    const int tid = threadIdx.x;
    const int tx = tid & 15;        // 0..15 -> 8 n-cols each
    const int ty = tid >> 4;        // 0..15 -> 8 m-rows each
    const int m0 = blockIdx.y * BM;
    const int n0 = blockIdx.x * BN;

    // load assignments
    const int arow = tid >> 1;          // 0..127 (m within tile)
    const int ak   = (tid & 1) * 8;     // 0 or 8  (k within tile)
    const int brow = tid >> 4;          // 0..15  (k within tile)
    const int bcol = (tid & 15) * 8;    // 0..120 (n within tile)

    const float* Aptr = A + (size_t)(m0 + arow) * K + ak;
    const float* Bptr = B + (size_t)brow * N + n0 + bcol;

    unsigned long long acc[8][4];
    #pragma unroll
    for (int i = 0; i < 8; i++)
        #pragma unroll
        for (int j = 0; j < 4; j++) acc[i][j] = 0ull;

    // prologue stage
    float4 a0 = *(const float4*)(Aptr);
    float4 a1 = *(const float4*)(Aptr + 4);
    float4 b0 = *(const float4*)(Bptr);
    float4 b1 = *(const float4*)(Bptr + 4);

    for (int k0 = 0; k0 < K; k0 += BK) {
        __syncthreads();   // previous slab fully consumed
        {
            float av[8] = {a0.x, a0.y, a0.z, a0.w, a1.x, a1.y, a1.z, a1.w};
            #pragma unroll
            for (int c = 0; c < 8; c++)
                *(float2*)(&Asd[ak + c][2 * arow]) = make_float2(av[c], av[c]);
            *(float4*)(&Bs[brow][bcol])     = b0;
            *(float4*)(&Bs[brow][bcol + 4]) = b1;
        }
        __syncthreads();

        // stage next slab (LDG latency hidden under the FFMA2 block below)
        if (k0 + BK < K) {
            a0 = *(const float4*)(Aptr + k0 + BK);
            a1 = *(const float4*)(Aptr + k0 + BK + 4);
            b0 = *(const float4*)(Bptr + (size_t)(k0 + BK) * N);
            b1 = *(const float4*)(Bptr + (size_t)(k0 + BK) * N + 4);
        }

        #pragma unroll
        for (int kk = 0; kk < BK; kk++) {
            ulonglong2 aA = *(const ulonglong2*)(&Asd[kk][16 * ty]);
            ulonglong2 aB = *(const ulonglong2*)(&Asd[kk][16 * ty + 4]);
            ulonglong2 aC = *(const ulonglong2*)(&Asd[kk][16 * ty + 8]);
            ulonglong2 aD = *(const ulonglong2*)(&Asd[kk][16 * ty + 12]);
            ulonglong2 bA = *(const ulonglong2*)(&Bs[kk][8 * tx]);
            ulonglong2 bB = *(const ulonglong2*)(&Bs[kk][8 * tx + 4]);
            unsigned long long ar[8] = {aA.x, aA.y, aB.x, aB.y, aC.x, aC.y, aD.x, aD.y};
            unsigned long long br[4] = {bA.x, bA.y, bB.x, bB.y};
            #pragma unroll
            for (int i = 0; i < 8; i++)
                #pragma unroll
                for (int j = 0; j < 4; j++)
                    ffma2(acc[i][j], ar[i], br[j]);
        }
    }

    // epilogue: + bias, store
    float2 bb[4];
    #pragma unroll
    for (int j = 0; j < 4; j++)
        bb[j] = *(const float2*)(bias + n0 + 8 * tx + 2 * j);
    #pragma unroll
    for (int i = 0; i < 8; i++) {
        float o[8];
        #pragma unroll
        for (int j = 0; j < 4; j++) {
            float lo, hi; unpack2(acc[i][j], lo, hi);
            o[2 * j]     = lo + bb[j].x;
            o[2 * j + 1] = hi + bb[j].y;
        }
        float* Crow = C + (size_t)(m0 + 8 * ty + i) * N + n0 + 8 * tx;
        *(float4*)(Crow)     = make_float4(o[0], o[1], o[2], o[3]);
        *(float4*)(Crow + 4) = make_float4(o[4], o[5], o[6], o[7]);
    }
}

// ---------------------------------------------------------------------------
// Flash attention, fp32 FFMA2, Dh=64.
// Block = 64 queries of one (b,h). 256 threads (16x16), 4x4 tiles, but the
// two inner-product loops run on fma.rn.f32x2 with duplicated broadcast
// operands held in shared memory:
//   Qtd : Q transposed, DUPLICATED  [d][2r]   (32 KB)
//   KP  : K transposed (swizzled)  16 KB, overlaid after softmax by
//         Pt duplicated [k][2r]                (32 KB region)
//   Vs  : V natural [k][d]                     (16 KB)
// 80 KB dynamic smem -> 2 CTAs/SM. XOR chunk swizzle keeps all stores/loads
// conflict-free (<=2-way worst case on the store phases).
// ---------------------------------------------------------------------------
__device__ __forceinline__ int swzoff(int d, int g) {   // K tile (16B groups)
    return d * 64 + ((g ^ ((d >> 2) & 15)) << 2);
}
__device__ __forceinline__ int gmask(int x) {           // dup tiles chunk mask
    return (x ^ (x >> 1)) & 31;
}
// duplicated-tile float offset for logical (row-major dim = x, dup'd dim = r)
__device__ __forceinline__ int dupoff(int x, int r) {
    return x * 128 + (((r >> 1) ^ gmask(x)) << 2) + (r & 1) * 2;
}

__global__ __launch_bounds__(256) void attn_kernel(
    const float* __restrict__ qkv,   // [M_TOT, 3*D_MODEL]
    float* __restrict__ out)         // [M_TOT, D_MODEL]
{
    extern __shared__ float sm[];
    float* Qtd = sm;            // 8192 floats
    float* KP  = sm + 8192;     // 8192 floats (Kt uses first 4096; Ptd all)
    float* Vs  = sm + 16384;    // 4096 floats

    const int tid = threadIdx.x;
    const int tx = tid & 15;        // key / d micro index
    const int ty = tid >> 4;        // query-row micro index
    const int q0 = blockIdx.x * 64;
    const int h  = blockIdx.y;
    const int b  = blockIdx.z;
    const int bT = b * SEQ;
    const int hoff = h * DH;

    // ---- load Q tile (transposed + duplicated + chunk-swizzled) ----
    #pragma unroll
    for (int it = 0; it < 4; it++) {
        int r  = (tid >> 4) + 16 * it;   // 0..63
        int ch = tid & 15;               // 4-float chunk along d
        float4 qv = *(const float4*)(qkv + (size_t)(bT + q0 + r) * (3 * D_MODEL) + hoff + ch * 4);
        float qa[4] = {qv.x, qv.y, qv.z, qv.w};
        #pragma unroll
        for (int i = 0; i < 4; i++) {
            int d = ch * 4 + i;
            *(float2*)(&Qtd[dupoff(d, r)]) = make_float2(qa[i], qa[i]);
        }
    }

    float m[4], l[4];
    unsigned long long o2[4][2];
    #pragma unroll
    for (int i = 0; i < 4; i++) {
        m[i] = -1e30f; l[i] = 0.f;
        o2[i][0] = 0ull; o2[i][1] = 0ull;
    }

    for (int kt = 0; kt < SEQ / 64; kt++) {
        const int k0 = kt * 64;
        __syncthreads();   // previous iteration's Ptd/Vs reads done (covers Qtd on kt=0)

        // ---- load K (transposed+swizzled) and V (natural) tiles ----
        #pragma unroll
        for (int it = 0; it < 4; it++) {
            int r  = (tid >> 4) + 16 * it;
            int ch = tid & 15;
            const float* src = qkv + (size_t)(bT + k0 + r) * (3 * D_MODEL) + hoff;
            float4 kv = *(const float4*)(src + D_MODEL + ch * 4);
            float4 vv = *(const float4*)(src + 2 * D_MODEL + ch * 4);
            float ka[4] = {kv.x, kv.y, kv.z, kv.w};
            #pragma unroll
            for (int i = 0; i < 4; i++) {
                int d = ch * 4 + i;
                KP[swzoff(d, r >> 2) + (r & 3)] = ka[i];
            }
            *(float4*)(&Vs[r * 64 + ch * 4]) = vv;
        }
        __syncthreads();

        // ---- S = Q K^T  (FFMA2: pairs along keys) ----
        unsigned long long s2[4][2];
        #pragma unroll
        for (int i = 0; i < 4; i++) { s2[i][0] = 0ull; s2[i][1] = 0ull; }

        #pragma unroll 16
        for (int d = 0; d < 64; d++) {
            int mk = gmask(d);
            ulonglong2 qA = *(const ulonglong2*)(&Qtd[d * 128 + (((2 * ty)     ^ mk) << 2)]);
            ulonglong2 qB = *(const ulonglong2*)(&Qtd[d * 128 + (((2 * ty + 1) ^ mk) << 2)]);
            ulonglong2 kv = *(const ulonglong2*)(&KP[swzoff(d, tx)]);
            unsigned long long ar[4] = {qA.x, qA.y, qB.x, qB.y};
            #pragma unroll
            for (int i = 0; i < 4; i++) {
                ffma2(s2[i][0], ar[i], kv.x);
                ffma2(s2[i][1], ar[i], kv.y);
            }
        }

        // ---- online softmax (scalar; row state replicated across 16 tx) ----
        float s[4][4];
        #pragma unroll
        for (int i = 0; i < 4; i++) {
            unpack2(s2[i][0], s[i][0], s[i][1]);
            unpack2(s2[i][1], s[i][2], s[i][3]);
        }
        const float scale = 0.125f;   // 1/sqrt(64)
        float alpha[4];
        #pragma unroll
        for (int i = 0; i < 4; i++) {
            float rm = -1e30f;
            #pragma unroll
            for (int j = 0; j < 4; j++) {
                s[i][j] *= scale;
                rm = fmaxf(rm, s[i][j]);
            }
            rm = fmaxf(rm, __shfl_xor_sync(0xffffffffu, rm, 1));
            rm = fmaxf(rm, __shfl_xor_sync(0xffffffffu, rm, 2));
            rm = fmaxf(rm, __shfl_xor_sync(0xffffffffu, rm, 4));
            rm = fmaxf(rm, __shfl_xor_sync(0xffffffffu, rm, 8));

            float mnew = fmaxf(m[i], rm);
            alpha[i] = __expf(m[i] - mnew);
            float rs = 0.f;
            #pragma unroll
            for (int j = 0; j < 4; j++) {
                s[i][j] = __expf(s[i][j] - mnew);   // s becomes P
                rs += s[i][j];
            }
            rs += __shfl_xor_sync(0xffffffffu, rs, 1);
            rs += __shfl_xor_sync(0xffffffffu, rs, 2);
            rs += __shfl_xor_sync(0xffffffffu, rs, 4);
            rs += __shfl_xor_sync(0xffffffffu, rs, 8);

            l[i] = l[i] * alpha[i] + rs;
            m[i] = mnew;
            unsigned long long al = pack2(alpha[i], alpha[i]);
            o2[i][0] = mul2(o2[i][0], al);
            o2[i][1] = mul2(o2[i][1], al);
        }

        __syncthreads();   // all K reads done before Ptd overwrites the region

        // ---- write P^T duplicated: Ptd[key k][2r dup] ----
        #pragma unroll
        for (int j = 0; j < 4; j++) {
            int kk = 4 * tx + j;
            #pragma unroll
            for (int i = 0; i < 4; i++) {
                int r = 4 * ty + i;
                *(float2*)(&KP[dupoff(kk, r)]) = make_float2(s[i][j], s[i][j]);
            }
        }
        __syncthreads();

        // ---- O += P V  (FFMA2: pairs along d-columns) ----
        #pragma unroll 16
        for (int k = 0; k < 64; k++) {
            int mk = gmask(k);
            ulonglong2 pA = *(const ulonglong2*)(&KP[k * 128 + (((2 * ty)     ^ mk) << 2)]);
            ulonglong2 pB = *(const ulonglong2*)(&KP[k * 128 + (((2 * ty + 1) ^ mk) << 2)]);
            ulonglong2 v2 = *(const ulonglong2*)(&Vs[k * 64 + 4 * tx]);
            unsigned long long ar[4] = {pA.x, pA.y, pB.x, pB.y};
            #pragma unroll
            for (int i = 0; i < 4; i++) {
                ffma2(o2[i][0], ar[i], v2.x);
                ffma2(o2[i][1], ar[i], v2.y);
            }
        }
    }

    // ---- normalize and store to [B,T,C] layout ----
    #pragma unroll
    for (int i = 0; i < 4; i++) {
        float inv = 1.0f / l[i];
        float o0, o1, o2l, o3;
        unpack2(o2[i][0], o0, o1);
        unpack2(o2[i][1], o2l, o3);
        float4 r = make_float4(o0 * inv, o1 * inv, o2l * inv, o3 * inv);
        *(float4*)(out + (size_t)(bT + q0 + 4 * ty + i) * D_MODEL + hoff + 4 * tx) = r;
    }
}

// ---------------------------------------------------------------------------
// Launch: qkv = x @ W_qkv + b_qkv ; flash-attn ; out = attn @ W_out + b_out
// ---------------------------------------------------------------------------
extern "C" void kernel_launch(void* const* d_in, const int* in_sizes, int n_in,
                              void* d_out, int out_size)
{
    (void)in_sizes; (void)n_in; (void)out_size;
    const float* x    = (const float*)d_in[0];
    const float* Wqkv = (const float*)d_in[1];
    const float* bqkv = (const float*)d_in[2];
    const float* Wout = (const float*)d_in[3];
    const float* bout = (const float*)d_in[4];
    float* out = (float*)d_out;

    float *qkv = nullptr, *attn = nullptr;
    cudaGetSymbolAddress((void**)&qkv,  g_qkv);
    cudaGetSymbolAddress((void**)&attn, g_attn);

    const int ATTN_SMEM = 80 * 1024;
    cudaFuncSetAttribute(attn_kernel,
                         cudaFuncAttributeMaxDynamicSharedMemorySize, ATTN_SMEM);

    dim3 blk(256);

    // GEMM1: [4096,1024] @ [1024,3072] + b
    sgemm_bias<<<dim3((3 * D_MODEL) / BN, M_TOT / BM), blk>>>(
        x, Wqkv, bqkv, qkv, M_TOT, 3 * D_MODEL, D_MODEL);

    // Attention: grid (q-tiles, heads, batch)
    attn_kernel<<<dim3(SEQ / 64, NH, BATCH), blk, ATTN_SMEM>>>(qkv, attn);

    // GEMM2: [4096,1024] @ [1024,1024] + b
    sgemm_bias<<<dim3(D_MODEL / BN, M_TOT / BM), blk>>>(
        attn, Wout, bout, out, M_TOT, D_MODEL, D_MODEL);
}

// round 11
// speedup vs baseline: 2.1596x; 2.1596x over previous
#include <cuda_runtime.h>
#include <cstdint>

#define D_MODEL 1024
#define SEQ     2048
#define BATCH   2
#define NH      16
#define DH      64
#define M_TOT   (BATCH * SEQ)   // 4096 rows

// Scratch (allocation-free rule: __device__ globals)
__device__ float g_qkv  [(size_t)M_TOT * 3 * D_MODEL];     // [4096, 3072]
__device__ float g_attn [(size_t)M_TOT * D_MODEL];         // [4096, 1024]
__device__ float g_xtf  [(size_t)M_TOT * D_MODEL];         // tf32-rounded x
__device__ float g_wqkvT[(size_t)3 * D_MODEL * D_MODEL];   // [3072, 1024] tf32
__device__ float g_woutT[(size_t)D_MODEL * D_MODEL];       // [1024, 1024] tf32

// ===========================================================================
// Helpers
// ===========================================================================
__device__ __forceinline__ uint32_t smem_u32(const void* p) {
    uint32_t a;
    asm("{ .reg .u64 t; cvta.to.shared.u64 t, %1; cvt.u32.u64 %0, t; }"
        : "=r"(a) : "l"(p));
    return a;
}
__device__ __forceinline__ float to_tf32(float x) {
    uint32_t u;
    asm("cvt.rna.tf32.f32 %0, %1;" : "=r"(u) : "f"(x));
    return __uint_as_float(u);
}
__device__ __forceinline__ float4 f4_tf32(float4 v) {
    v.x = to_tf32(v.x); v.y = to_tf32(v.y); v.z = to_tf32(v.z); v.w = to_tf32(v.w);
    return v;
}

#define CP_ASYNC16(saddr, gptr) \
    asm volatile("cp.async.cg.shared.global [%0], [%1], 16;" \
                 :: "r"(saddr), "l"(gptr) : "memory")
#define CP_COMMIT() asm volatile("cp.async.commit_group;" ::: "memory")

// D(16x8) += A(16x8, row) * B(8x8, col)  tf32 inputs, fp32 accumulate
#define MMA_TF32(c, a, b) \
    asm volatile("mma.sync.aligned.m16n8k8.row.col.f32.tf32.tf32.f32 " \
        "{%0,%1,%2,%3}, {%4,%5,%6,%7}, {%8,%9}, {%0,%1,%2,%3};" \
        : "+f"((c)[0]), "+f"((c)[1]), "+f"((c)[2]), "+f"((c)[3]) \
        : "r"((a)[0]), "r"((a)[1]), "r"((a)[2]), "r"((a)[3]), \
          "r"((b)[0]), "r"((b)[1]))

// ===========================================================================
// x -> tf32-rounded copy
// ===========================================================================
__global__ void cvt_tf32_k(const float* __restrict__ in, float* __restrict__ out)
{
    int i = (blockIdx.x * blockDim.x + threadIdx.x) * 4;
    *(float4*)(out + i) = f4_tf32(*(const float4*)(in + i));
}

// ===========================================================================
// Transpose + tf32 round: out[C,R] = tf32(in[R,C]^T)
// ===========================================================================
__global__ void transpose_k(const float* __restrict__ in, float* __restrict__ out,
                            int R, int C)
{
    __shared__ float t[32][33];
    int tx = threadIdx.x, ty = threadIdx.y;
    int c0 = blockIdx.x * 32, r0 = blockIdx.y * 32;
    #pragma unroll
    for (int j = 0; j < 4; j++)
        t[ty + 8 * j][tx] = in[(size_t)(r0 + ty + 8 * j) * C + c0 + tx];
    __syncthreads();
    #pragma unroll
    for (int j = 0; j < 4; j++)
        out[(size_t)(c0 + ty + 8 * j) * R + r0 + tx] = to_tf32(t[tx][ty + 8 * j]);
}

// ===========================================================================
// mma.sync tf32 GEMM + bias: C[M,N] = A[M,K] @ Bt[N,K]^T + bias[N]
// A, Bt already tf32-rounded. 128x128 CTA tile, 8 warps (4 M x 2 N),
// warp tile 32x64, m16n8k8 fragments. K staged 32 per cp.async group,
// double buffered. Smem rows padded to 36 floats -> every fragment LDS
// hits bank (4*grp+qd) == lane: conflict-free.
// ===========================================================================
#define KS       32
#define ASTRIDE  36                       // floats per smem row
#define AROWB    (ASTRIDE * 4)            // 144 bytes
#define TILE_F   (128 * ASTRIDE)          // floats per operand tile
#define TILE_BB  (TILE_F * 4)             // 18432 bytes
#define STAGE_B  (2 * TILE_BB)            // A + B per stage
#define GEMM_SMEM (2 * STAGE_B)           // double buffer: 73728 B

__device__ __forceinline__ void stage_load(uint32_t sA, uint32_t sB,
                                           const float* ga, const float* gb, int K)
{
    #pragma unroll
    for (int it = 0; it < 4; it++) {
        CP_ASYNC16(sA + it * 32 * AROWB, ga + (size_t)(32 * it) * K);
        CP_ASYNC16(sB + it * 32 * AROWB, gb + (size_t)(32 * it) * K);
    }
    CP_COMMIT();
}

__global__ __launch_bounds__(256, 2) void gemm_tc(
    const float* __restrict__ A, const float* __restrict__ Bt,
    const float* __restrict__ bias, float* __restrict__ C,
    int N, int K)
{
    extern __shared__ float smf[];
    const uint32_t sbase = smem_u32(smf);

    const int tid  = threadIdx.x;
    const int wid  = tid >> 5;
    const int lane = tid & 31;
    const int grp  = lane >> 2;      // 0..7
    const int qd   = lane & 3;       // 0..3
    const int wm   = wid & 3;        // warp M index (4)
    const int wn   = wid >> 2;       // warp N index (2)
    const int m0   = blockIdx.y * 128;
    const int n0   = blockIdx.x * 128;

    // cp.async source/dest for this thread (row = tid>>3, 16B chunk = tid&7)
    const float* Ag = A  + (size_t)(m0 + (tid >> 3)) * K + (tid & 7) * 4;
    const float* Bg = Bt + (size_t)(n0 + (tid >> 3)) * K + (tid & 7) * 4;
    const uint32_t dA = sbase + (tid >> 3) * AROWB + (tid & 7) * 16;
    const uint32_t dB = dA + TILE_BB;

    const int NS = K / KS;   // 32

    float acc[2][8][4] = {};

    stage_load(dA, dB, Ag, Bg, K);
    stage_load(dA + STAGE_B, dB + STAGE_B, Ag + KS, Bg + KS, K);

    for (int s = 0; s < NS; s++) {
        if (s + 1 < NS) asm volatile("cp.async.wait_group 1;" ::: "memory");
        else            asm volatile("cp.async.wait_group 0;" ::: "memory");
        __syncthreads();

        const float* As = smf + (s & 1) * (STAGE_B / 4);
        const float* Bs = As + TILE_F;

        #pragma unroll
        for (int ks = 0; ks < 4; ks++) {
            uint32_t a[2][4], b[8][2];
            #pragma unroll
            for (int mb = 0; mb < 2; mb++) {
                const int row = wm * 32 + mb * 16 + grp;
                const uint32_t* p0 = (const uint32_t*)&As[row * ASTRIDE + ks * 8 + qd];
                const uint32_t* p1 = (const uint32_t*)&As[(row + 8) * ASTRIDE + ks * 8 + qd];
                a[mb][0] = p0[0]; a[mb][1] = p1[0];
                a[mb][2] = p0[4]; a[mb][3] = p1[4];
            }
            #pragma unroll
            for (int nb = 0; nb < 8; nb++) {
                const int rn = wn * 64 + nb * 8 + grp;
                const uint32_t* p = (const uint32_t*)&Bs[rn * ASTRIDE + ks * 8 + qd];
                b[nb][0] = p[0]; b[nb][1] = p[4];
            }
            #pragma unroll
            for (int mb = 0; mb < 2; mb++)
                #pragma unroll
                for (int nb = 0; nb < 8; nb++)
                    MMA_TF32(acc[mb][nb], a[mb], b[nb]);
        }
        __syncthreads();
        if (s + 2 < NS)
            stage_load(dA + ((s + 2) & 1) * STAGE_B, dB + ((s + 2) & 1) * STAGE_B,
                       Ag + (size_t)(s + 2) * KS, Bg + (size_t)(s + 2) * KS, K);
    }

    // epilogue: + bias, fp32 store
    const float* brow = bias + n0 + wn * 64;
    #pragma unroll
    for (int mb = 0; mb < 2; mb++) {
        #pragma unroll
        for (int half = 0; half < 2; half++) {
            const int row = m0 + wm * 32 + mb * 16 + grp + half * 8;
            float* crow = C + (size_t)row * N + n0 + wn * 64;
            #pragma unroll
            for (int nb = 0; nb < 8; nb++) {
                float2 bb = *(const float2*)(brow + nb * 8 + 2 * qd);
                float2 o;
                o.x = acc[mb][nb][half * 2 + 0] + bb.x;
                o.y = acc[mb][nb][half * 2 + 1] + bb.y;
                *(float2*)(crow + nb * 8 + 2 * qd) = o;
            }
        }
    }
}

// ===========================================================================
// Flash attention, fp32, Dh=64 (proven round-7 kernel; output tf32-rounded
// so GEMM2 can consume it directly).
// ===========================================================================
__device__ __forceinline__ int swzoff(int d, int g) {
    return d * 64 + (((g ^ ((d >> 2) & 15)) << 2));
}

__global__ __launch_bounds__(256) void attn_kernel(
    const float* __restrict__ qkv,   // [M_TOT, 3*D_MODEL]
    float* __restrict__ out)         // [M_TOT, D_MODEL]
{
    __shared__ float Qt[64 * 64];
    __shared__ float Kt[64 * 64];   // aliased as Pt after S is computed
    __shared__ float Vs[64 * 64];

    const int tid = threadIdx.x;
    const int tx = tid & 15;
    const int ty = tid >> 4;
    const int q0 = blockIdx.x * 64;
    const int h  = blockIdx.y;
    const int b  = blockIdx.z;
    const int bT = b * SEQ;
    const int hoff = h * DH;

    #pragma unroll
    for (int it = 0; it < 4; it++) {
        int r  = (tid >> 4) + 16 * it;
        int ch = tid & 15;
        float4 qv = *(const float4*)(qkv + (size_t)(bT + q0 + r) * (3 * D_MODEL) + hoff + ch * 4);
        float qa[4] = {qv.x, qv.y, qv.z, qv.w};
        #pragma unroll
        for (int i = 0; i < 4; i++) {
            int d = ch * 4 + i;
            Qt[swzoff(d, r >> 2) + (r & 3)] = qa[i];
        }
    }

    float m[4], l[4], o[4][4];
    #pragma unroll
    for (int i = 0; i < 4; i++) {
        m[i] = -1e30f;
        l[i] = 0.f;
        #pragma unroll
        for (int j = 0; j < 4; j++) o[i][j] = 0.f;
    }

    for (int kt = 0; kt < SEQ / 64; kt++) {
        const int k0 = kt * 64;
        __syncthreads();

        #pragma unroll
        for (int it = 0; it < 4; it++) {
            int r  = (tid >> 4) + 16 * it;
            int ch = tid & 15;
            const float* src = qkv + (size_t)(bT + k0 + r) * (3 * D_MODEL) + hoff;
            float4 kv = *(const float4*)(src + D_MODEL + ch * 4);
            float4 vv = *(const float4*)(src + 2 * D_MODEL + ch * 4);
            float ka[4] = {kv.x, kv.y, kv.z, kv.w};
            #pragma unroll
            for (int i = 0; i < 4; i++) {
                int d = ch * 4 + i;
                Kt[swzoff(d, r >> 2) + (r & 3)] = ka[i];
            }
            *(float4*)(&Vs[r * 64 + ch * 4]) = vv;
        }
        __syncthreads();

        float s[4][4] = {};
        #pragma unroll
        for (int d = 0; d < 64; d++) {
            float4 a4 = *(const float4*)(&Qt[swzoff(d, ty)]);
            float4 b4 = *(const float4*)(&Kt[swzoff(d, tx)]);
            float ar[4] = {a4.x, a4.y, a4.z, a4.w};
            float br[4] = {b4.x, b4.y, b4.z, b4.w};
            #pragma unroll
            for (int i = 0; i < 4; i++)
                #pragma unroll
                for (int j = 0; j < 4; j++)
                    s[i][j] = fmaf(ar[i], br[j], s[i][j]);
        }

        const float scale = 0.125f;
        #pragma unroll
        for (int i = 0; i < 4; i++) {
            float rm = -1e30f;
            #pragma unroll
            for (int j = 0; j < 4; j++) {
                s[i][j] *= scale;
                rm = fmaxf(rm, s[i][j]);
            }
            rm = fmaxf(rm, __shfl_xor_sync(0xffffffffu, rm, 1));
            rm = fmaxf(rm, __shfl_xor_sync(0xffffffffu, rm, 2));
            rm = fmaxf(rm, __shfl_xor_sync(0xffffffffu, rm, 4));
            rm = fmaxf(rm, __shfl_xor_sync(0xffffffffu, rm, 8));

            float mnew = fmaxf(m[i], rm);
            float alpha = __expf(m[i] - mnew);
            float rs = 0.f;
            #pragma unroll
            for (int j = 0; j < 4; j++) {
                s[i][j] = __expf(s[i][j] - mnew);
                rs += s[i][j];
            }
            rs += __shfl_xor_sync(0xffffffffu, rs, 1);
            rs += __shfl_xor_sync(0xffffffffu, rs, 2);
            rs += __shfl_xor_sync(0xffffffffu, rs, 4);
            rs += __shfl_xor_sync(0xffffffffu, rs, 8);

            l[i] = l[i] * alpha + rs;
            m[i] = mnew;
            #pragma unroll
            for (int j = 0; j < 4; j++) o[i][j] *= alpha;
        }

        __syncthreads();

        #pragma unroll
        for (int j = 0; j < 4; j++) {
            int kk = tx * 4 + j;
            float4 pv = make_float4(s[0][j], s[1][j], s[2][j], s[3][j]);
            *(float4*)(&Kt[swzoff(kk, ty)]) = pv;
        }
        __syncthreads();

        #pragma unroll
        for (int k = 0; k < 64; k++) {
            float4 a4 = *(const float4*)(&Kt[swzoff(k, ty)]);
            float4 v4 = *(const float4*)(&Vs[k * 64 + tx * 4]);
            float ar[4] = {a4.x, a4.y, a4.z, a4.w};
            float vr[4] = {v4.x, v4.y, v4.z, v4.w};
            #pragma unroll
            for (int i = 0; i < 4; i++)
                #pragma unroll
                for (int j = 0; j < 4; j++)
                    o[i][j] = fmaf(ar[i], vr[j], o[i][j]);
        }
    }

    // tf32-round the output so GEMM2 reads pre-converted A
    #pragma unroll
    for (int i = 0; i < 4; i++) {
        float inv = 1.0f / l[i];
        float4 r;
        r.x = to_tf32(o[i][0] * inv);
        r.y = to_tf32(o[i][1] * inv);
        r.z = to_tf32(o[i][2] * inv);
        r.w = to_tf32(o[i][3] * inv);
        *(float4*)(out + (size_t)(bT + q0 + ty * 4 + i) * D_MODEL + hoff + tx * 4) = r;
    }
}

// ===========================================================================
// Launch
// ===========================================================================
extern "C" void kernel_launch(void* const* d_in, const int* in_sizes, int n_in,
                              void* d_out, int out_size)
{
    (void)in_sizes; (void)n_in; (void)out_size;
    const float* x    = (const float*)d_in[0];
    const float* Wqkv = (const float*)d_in[1];
    const float* bqkv = (const float*)d_in[2];
    const float* Wout = (const float*)d_in[3];
    const float* bout = (const float*)d_in[4];
    float* out = (float*)d_out;

    float *qkv, *attn, *xtf, *wqkvT, *woutT;
    cudaGetSymbolAddress((void**)&qkv,   g_qkv);
    cudaGetSymbolAddress((void**)&attn,  g_attn);
    cudaGetSymbolAddress((void**)&xtf,   g_xtf);
    cudaGetSymbolAddress((void**)&wqkvT, g_wqkvT);
    cudaGetSymbolAddress((void**)&woutT, g_woutT);

    cudaFuncSetAttribute(gemm_tc,
                         cudaFuncAttributeMaxDynamicSharedMemorySize, GEMM_SMEM);

    // tf32-round x; transpose + tf32-round weights
    cvt_tf32_k<<<(M_TOT * D_MODEL) / (256 * 4), 256>>>(x, xtf);
    transpose_k<<<dim3((3 * D_MODEL) / 32, D_MODEL / 32), dim3(32, 8)>>>(
        Wqkv, wqkvT, D_MODEL, 3 * D_MODEL);
    transpose_k<<<dim3(D_MODEL / 32, D_MODEL / 32), dim3(32, 8)>>>(
        Wout, woutT, D_MODEL, D_MODEL);

    // GEMM1: qkv = x @ Wqkv + b   (tensor cores, mma.sync tf32)
    gemm_tc<<<dim3((3 * D_MODEL) / 128, M_TOT / 128), 256, GEMM_SMEM>>>(
        xtf, wqkvT, bqkv, qkv, 3 * D_MODEL, D_MODEL);

    // Attention (fp32 flash, round-7 kernel)
    attn_kernel<<<dim3(SEQ / 64, NH, BATCH), 256>>>(qkv, attn);

    // GEMM2: out = attn @ Wout + b
    gemm_tc<<<dim3(D_MODEL / 128, M_TOT / 128), 256, GEMM_SMEM>>>(
        attn, woutT, bout, out, D_MODEL, D_MODEL);
}

// round 13
// speedup vs baseline: 4.5291x; 2.0971x over previous
#include <cuda_runtime.h>
#include <cstdint>

#define D_MODEL 1024
#define SEQ     2048
#define BATCH   2
#define NH      16
#define DH      64
#define M_TOT   (BATCH * SEQ)   // 4096 rows

// Scratch (allocation-free rule: __device__ globals)
__device__ float g_qkv  [(size_t)M_TOT * 3 * D_MODEL];     // [4096, 3072] tf32-rounded
__device__ float g_attn [(size_t)M_TOT * D_MODEL];         // [4096, 1024] tf32-rounded
__device__ float g_xtf  [(size_t)M_TOT * D_MODEL];         // tf32-rounded x
__device__ float g_wqkvT[(size_t)3 * D_MODEL * D_MODEL];   // [3072, 1024] tf32
__device__ float g_woutT[(size_t)D_MODEL * D_MODEL];       // [1024, 1024] tf32

// ===========================================================================
// Helpers
// ===========================================================================
__device__ __forceinline__ uint32_t smem_u32(const void* p) {
    uint32_t a;
    asm("{ .reg .u64 t; cvta.to.shared.u64 t, %1; cvt.u32.u64 %0, t; }"
        : "=r"(a) : "l"(p));
    return a;
}
__device__ __forceinline__ float to_tf32(float x) {
    uint32_t u;
    asm("cvt.rna.tf32.f32 %0, %1;" : "=r"(u) : "f"(x));
    return __uint_as_float(u);
}
__device__ __forceinline__ uint32_t tf32bits(float x) {
    uint32_t u;
    asm("cvt.rna.tf32.f32 %0, %1;" : "=r"(u) : "f"(x));
    return u;
}
__device__ __forceinline__ float4 f4_tf32(float4 v) {
    v.x = to_tf32(v.x); v.y = to_tf32(v.y); v.z = to_tf32(v.z); v.w = to_tf32(v.w);
    return v;
}
__device__ __forceinline__ float ex2f(float x) {
    float r;
    asm("ex2.approx.f32 %0, %1;" : "=f"(r) : "f"(x));
    return r;
}

#define CP_ASYNC16(saddr, gptr) \
    asm volatile("cp.async.cg.shared.global [%0], [%1], 16;" \
                 :: "r"(saddr), "l"(gptr) : "memory")
#define CP_COMMIT() asm volatile("cp.async.commit_group;" ::: "memory")

// D(16x8) += A(16x8, row) * B(8x8, col)  tf32 inputs, fp32 accumulate
#define MMA_TF32(c, a, b) \
    asm volatile("mma.sync.aligned.m16n8k8.row.col.f32.tf32.tf32.f32 " \
        "{%0,%1,%2,%3}, {%4,%5,%6,%7}, {%8,%9}, {%0,%1,%2,%3};" \
        : "+f"((c)[0]), "+f"((c)[1]), "+f"((c)[2]), "+f"((c)[3]) \
        : "r"((a)[0]), "r"((a)[1]), "r"((a)[2]), "r"((a)[3]), \
          "r"((b)[0]), "r"((b)[1]))

// ===========================================================================
// x -> tf32-rounded copy
// ===========================================================================
__global__ void cvt_tf32_k(const float* __restrict__ in, float* __restrict__ out)
{
    int i = (blockIdx.x * blockDim.x + threadIdx.x) * 4;
    *(float4*)(out + i) = f4_tf32(*(const float4*)(in + i));
}

// ===========================================================================
// Transpose + tf32 round: out[C,R] = tf32(in[R,C]^T)
// ===========================================================================
__global__ void transpose_k(const float* __restrict__ in, float* __restrict__ out,
                            int R, int C)
{
    __shared__ float t[32][33];
    int tx = threadIdx.x, ty = threadIdx.y;
    int c0 = blockIdx.x * 32, r0 = blockIdx.y * 32;
    #pragma unroll
    for (int j = 0; j < 4; j++)
        t[ty + 8 * j][tx] = in[(size_t)(r0 + ty + 8 * j) * C + c0 + tx];
    __syncthreads();
    #pragma unroll
    for (int j = 0; j < 4; j++)
        out[(size_t)(c0 + ty + 8 * j) * R + r0 + tx] = to_tf32(t[tx][ty + 8 * j]);
}

// ===========================================================================
// mma.sync tf32 GEMM + bias (proven R11 kernel). RND: tf32-round the output
// (used for GEMM1 so attention consumes exact tf32 bits via cp.async).
// ===========================================================================
#define KS       32
#define ASTRIDE  36
#define AROWB    (ASTRIDE * 4)
#define TILE_F   (128 * ASTRIDE)
#define TILE_BB  (TILE_F * 4)
#define STAGE_B  (2 * TILE_BB)
#define GEMM_SMEM (2 * STAGE_B)           // 73728 B

__device__ __forceinline__ void stage_load(uint32_t sA, uint32_t sB,
                                           const float* ga, const float* gb, int K)
{
    #pragma unroll
    for (int it = 0; it < 4; it++) {
        CP_ASYNC16(sA + it * 32 * AROWB, ga + (size_t)(32 * it) * K);
        CP_ASYNC16(sB + it * 32 * AROWB, gb + (size_t)(32 * it) * K);
    }
    CP_COMMIT();
}

template<bool RND>
__global__ __launch_bounds__(256, 2) void gemm_tc(
    const float* __restrict__ A, const float* __restrict__ Bt,
    const float* __restrict__ bias, float* __restrict__ C,
    int N, int K)
{
    extern __shared__ float smf[];
    const uint32_t sbase = smem_u32(smf);

    const int tid  = threadIdx.x;
    const int wid  = tid >> 5;
    const int lane = tid & 31;
    const int grp  = lane >> 2;
    const int qd   = lane & 3;
    const int wm   = wid & 3;
    const int wn   = wid >> 2;
    const int m0   = blockIdx.y * 128;
    const int n0   = blockIdx.x * 128;

    const float* Ag = A  + (size_t)(m0 + (tid >> 3)) * K + (tid & 7) * 4;
    const float* Bg = Bt + (size_t)(n0 + (tid >> 3)) * K + (tid & 7) * 4;
    const uint32_t dA = sbase + (tid >> 3) * AROWB + (tid & 7) * 16;
    const uint32_t dB = dA + TILE_BB;

    const int NS = K / KS;

    float acc[2][8][4] = {};

    stage_load(dA, dB, Ag, Bg, K);
    stage_load(dA + STAGE_B, dB + STAGE_B, Ag + KS, Bg + KS, K);

    for (int s = 0; s < NS; s++) {
        if (s + 1 < NS) asm volatile("cp.async.wait_group 1;" ::: "memory");
        else            asm volatile("cp.async.wait_group 0;" ::: "memory");
        __syncthreads();

        const float* As = smf + (s & 1) * (STAGE_B / 4);
        const float* Bs = As + TILE_F;

        #pragma unroll
        for (int ks = 0; ks < 4; ks++) {
            uint32_t a[2][4], b[8][2];
            #pragma unroll
            for (int mb = 0; mb < 2; mb++) {
                const int row = wm * 32 + mb * 16 + grp;
                const uint32_t* p0 = (const uint32_t*)&As[row * ASTRIDE + ks * 8 + qd];
                const uint32_t* p1 = (const uint32_t*)&As[(row + 8) * ASTRIDE + ks * 8 + qd];
                a[mb][0] = p0[0]; a[mb][1] = p1[0];
                a[mb][2] = p0[4]; a[mb][3] = p1[4];
            }
            #pragma unroll
            for (int nb = 0; nb < 8; nb++) {
                const int rn = wn * 64 + nb * 8 + grp;
                const uint32_t* p = (const uint32_t*)&Bs[rn * ASTRIDE + ks * 8 + qd];
                b[nb][0] = p[0]; b[nb][1] = p[4];
            }
            #pragma unroll
            for (int mb = 0; mb < 2; mb++)
                #pragma unroll
                for (int nb = 0; nb < 8; nb++)
                    MMA_TF32(acc[mb][nb], a[mb], b[nb]);
        }
        __syncthreads();
        if (s + 2 < NS)
            stage_load(dA + ((s + 2) & 1) * STAGE_B, dB + ((s + 2) & 1) * STAGE_B,
                       Ag + (size_t)(s + 2) * KS, Bg + (size_t)(s + 2) * KS, K);
    }

    const float* brow = bias + n0 + wn * 64;
    #pragma unroll
    for (int mb = 0; mb < 2; mb++) {
        #pragma unroll
        for (int half = 0; half < 2; half++) {
            const int row = m0 + wm * 32 + mb * 16 + grp + half * 8;
            float* crow = C + (size_t)row * N + n0 + wn * 64;
            #pragma unroll
            for (int nb = 0; nb < 8; nb++) {
                float2 bb = *(const float2*)(brow + nb * 8 + 2 * qd);
                float2 o;
                o.x = acc[mb][nb][half * 2 + 0] + bb.x;
                o.y = acc[mb][nb][half * 2 + 1] + bb.y;
                if (RND) { o.x = to_tf32(o.x); o.y = to_tf32(o.y); }
                *(float2*)(crow + nb * 8 + 2 * qd) = o;
            }
        }
    }
}

// ===========================================================================
// Flash attention on mma.sync tf32.
// CTA = 128 queries of one (b,h); 8 warps, each owns a 16-query m16 strip.
// Keys in tiles of 64, K/V double-buffered via cp.async. Q resident in smem.
//   Qs [128][68]  (stride 68 -> A-frag bank = 4*grp+qd+8kb : conflict-free)
//   Ks [2][64][68] (B-frag bank = 4*grp+qd+8kb : conflict-free)
//   Vs [2][64][72] (stride 72 -> B-frag bank = 8*qd+grp : conflict-free)
// Softmax rows live in quads (2 shfl.xor reductions). P converted from mma
// C-layout to A-layout with 8 quad-shuffles per k-block (no smem trip).
// 106496 B dynamic smem -> 2 CTAs/SM.
// ===========================================================================
#define ATTN_SMEM 106496

__global__ __launch_bounds__(256, 2) void attn_tc(
    const float* __restrict__ qkv,   // [M_TOT, 3*D_MODEL] tf32-rounded
    float* __restrict__ out)         // [M_TOT, D_MODEL]
{
    extern __shared__ float sm[];
    float* Qs = sm;                   // 128*68 = 8704 floats
    float* Ks = sm + 8704;            // 2*64*68 = 8704 floats
    float* Vs = sm + 17408;           // 2*64*72 = 9216 floats

    const uint32_t sbase = smem_u32(sm);
    const uint32_t KsU = sbase + 8704u * 4u;
    const uint32_t VsU = sbase + 17408u * 4u;

    const int tid  = threadIdx.x;
    const int wid  = tid >> 5;
    const int lane = tid & 31;
    const int grp  = lane >> 2;
    const int qd   = lane & 3;
    const int q0   = blockIdx.x * 128;
    const int hoff = blockIdx.y * DH;
    const int bT   = blockIdx.z * SEQ;

    const int lrow = tid >> 4;        // 0..15
    const int lch  = tid & 15;        // 16B chunk within 64-float row

    // ---- stage K/V tile (64 keys) into buffer p ----
    auto stage_kv = [&](int p, int k0) {
        const float* kg = qkv + (size_t)(bT + k0 + lrow) * 3072 + 1024 + hoff + lch * 4;
        uint32_t dk = KsU + (uint32_t)p * 17408u + lrow * 272u + lch * 16u;
        uint32_t dv = VsU + (uint32_t)p * 18432u + lrow * 288u + lch * 16u;
        #pragma unroll
        for (int it = 0; it < 4; it++) {
            CP_ASYNC16(dk + it * 16 * 272, kg + (size_t)it * 16 * 3072);
            CP_ASYNC16(dv + it * 16 * 288, kg + 1024 + (size_t)it * 16 * 3072);
        }
        CP_COMMIT();
    };

    stage_kv(0, 0);
    stage_kv(1, 64);

    // ---- load Q tile (128 x 64) ----
    #pragma unroll
    for (int it = 0; it < 8; it++) {
        int row = lrow + 16 * it;
        float4 v = *(const float4*)(qkv + (size_t)(bT + q0 + row) * 3072 + hoff + lch * 4);
        *(float4*)(&Qs[row * 68 + lch * 4]) = v;
    }

    float m0 = -1e30f, m1 = -1e30f, l0 = 0.f, l1 = 0.f;
    float o[8][4] = {};

    const float* qp = Qs + (16 * wid + grp) * 68 + qd;
    const int src_lo = (lane & 28) | (qd >> 1);
    const int src_hi = src_lo + 2;
    const bool odd = qd & 1;

    for (int kt = 0; kt < SEQ / 64; kt++) {
        const int p = kt & 1;
        if (kt + 1 < SEQ / 64) asm volatile("cp.async.wait_group 1;" ::: "memory");
        else                   asm volatile("cp.async.wait_group 0;" ::: "memory");
        __syncthreads();

        const float* kp = Ks + p * 4352 + grp * 68 + qd;
        const float* vp = Vs + p * 4608 + qd * 72 + grp;

        // ---- S = Q K^T : 64 mma ----
        float s[8][4] = {};
        #pragma unroll
        for (int kb = 0; kb < 8; kb++) {
            uint32_t a[4];
            a[0] = __float_as_uint(qp[8 * kb]);
            a[1] = __float_as_uint(qp[544 + 8 * kb]);
            a[2] = __float_as_uint(qp[8 * kb + 4]);
            a[3] = __float_as_uint(qp[544 + 8 * kb + 4]);
            const float* kpp = kp + 8 * kb;
            #pragma unroll
            for (int nb = 0; nb < 8; nb++) {
                uint32_t b[2];
                b[0] = __float_as_uint(kpp[nb * 544]);
                b[1] = __float_as_uint(kpp[nb * 544 + 4]);
                MMA_TF32(s[nb], a, b);
            }
        }

        // ---- online softmax (base-2; rows grp / grp+8 live in quads) ----
        const float c1 = 0.18033688011112042f;   // (1/8) * log2(e)
        float t0 = -1e30f, t1 = -1e30f;
        #pragma unroll
        for (int nb = 0; nb < 8; nb++) {
            s[nb][0] *= c1; s[nb][1] *= c1; s[nb][2] *= c1; s[nb][3] *= c1;
            t0 = fmaxf(t0, fmaxf(s[nb][0], s[nb][1]));
            t1 = fmaxf(t1, fmaxf(s[nb][2], s[nb][3]));
        }
        t0 = fmaxf(t0, __shfl_xor_sync(0xffffffffu, t0, 1));
        t0 = fmaxf(t0, __shfl_xor_sync(0xffffffffu, t0, 2));
        t1 = fmaxf(t1, __shfl_xor_sync(0xffffffffu, t1, 1));
        t1 = fmaxf(t1, __shfl_xor_sync(0xffffffffu, t1, 2));

        float mn0 = fmaxf(m0, t0), mn1 = fmaxf(m1, t1);
        float al0 = ex2f(m0 - mn0), al1 = ex2f(m1 - mn1);
        m0 = mn0; m1 = mn1;

        float rs0 = 0.f, rs1 = 0.f;
        #pragma unroll
        for (int nb = 0; nb < 8; nb++) {
            s[nb][0] = ex2f(s[nb][0] - mn0);
            s[nb][1] = ex2f(s[nb][1] - mn0);
            s[nb][2] = ex2f(s[nb][2] - mn1);
            s[nb][3] = ex2f(s[nb][3] - mn1);
            rs0 += s[nb][0] + s[nb][1];
            rs1 += s[nb][2] + s[nb][3];
        }
        rs0 += __shfl_xor_sync(0xffffffffu, rs0, 1);
        rs0 += __shfl_xor_sync(0xffffffffu, rs0, 2);
        rs1 += __shfl_xor_sync(0xffffffffu, rs1, 1);
        rs1 += __shfl_xor_sync(0xffffffffu, rs1, 2);
        l0 = l0 * al0 + rs0;
        l1 = l1 * al1 + rs1;

        #pragma unroll
        for (int nb = 0; nb < 8; nb++) {
            o[nb][0] *= al0; o[nb][1] *= al0;
            o[nb][2] *= al1; o[nb][3] *= al1;
        }

        // ---- O += P V : per kb, convert P C-frag -> A-frag via quad shfl ----
        #pragma unroll
        for (int kb = 0; kb < 8; kb++) {
            float x0 = __shfl_sync(0xffffffffu, s[kb][0], src_lo);
            float x1 = __shfl_sync(0xffffffffu, s[kb][1], src_lo);
            float y0 = __shfl_sync(0xffffffffu, s[kb][0], src_hi);
            float y1 = __shfl_sync(0xffffffffu, s[kb][1], src_hi);
            float z0 = __shfl_sync(0xffffffffu, s[kb][2], src_lo);
            float z1 = __shfl_sync(0xffffffffu, s[kb][3], src_lo);
            float w0 = __shfl_sync(0xffffffffu, s[kb][2], src_hi);
            float w1 = __shfl_sync(0xffffffffu, s[kb][3], src_hi);
            uint32_t a[4];
            a[0] = tf32bits(odd ? x1 : x0);   // row grp,   col qd
            a[1] = tf32bits(odd ? z1 : z0);   // row grp+8, col qd
            a[2] = tf32bits(odd ? y1 : y0);   // row grp,   col qd+4
            a[3] = tf32bits(odd ? w1 : w0);   // row grp+8, col qd+4
            const float* vpp = vp + kb * 576;
            #pragma unroll
            for (int nb = 0; nb < 8; nb++) {
                uint32_t b[2];
                b[0] = __float_as_uint(vpp[nb * 8]);
                b[1] = __float_as_uint(vpp[nb * 8 + 288]);
                MMA_TF32(o[nb], a, b);
            }
        }

        __syncthreads();
        if (kt + 2 < SEQ / 64) stage_kv(p, (kt + 2) * 64);
    }

    // ---- normalize + tf32-round (GEMM2 input) + store ----
    const float inv0 = 1.0f / l0, inv1 = 1.0f / l1;
    const int r0 = bT + q0 + 16 * wid + grp;
    float* p0 = out + (size_t)r0 * D_MODEL + hoff + 2 * qd;
    float* p1 = p0 + (size_t)8 * D_MODEL;
    #pragma unroll
    for (int nb = 0; nb < 8; nb++) {
        float2 lo, hi;
        lo.x = to_tf32(o[nb][0] * inv0); lo.y = to_tf32(o[nb][1] * inv0);
        hi.x = to_tf32(o[nb][2] * inv1); hi.y = to_tf32(o[nb][3] * inv1);
        *(float2*)(p0 + 8 * nb) = lo;
        *(float2*)(p1 + 8 * nb) = hi;
    }
}

// ===========================================================================
// Launch
// ===========================================================================
extern "C" void kernel_launch(void* const* d_in, const int* in_sizes, int n_in,
                              void* d_out, int out_size)
{
    (void)in_sizes; (void)n_in; (void)out_size;
    const float* x    = (const float*)d_in[0];
    const float* Wqkv = (const float*)d_in[1];
    const float* bqkv = (const float*)d_in[2];
    const float* Wout = (const float*)d_in[3];
    const float* bout = (const float*)d_in[4];
    float* out = (float*)d_out;

    float *qkv, *attn, *xtf, *wqkvT, *woutT;
    cudaGetSymbolAddress((void**)&qkv,   g_qkv);
    cudaGetSymbolAddress((void**)&attn,  g_attn);
    cudaGetSymbolAddress((void**)&xtf,   g_xtf);
    cudaGetSymbolAddress((void**)&wqkvT, g_wqkvT);
    cudaGetSymbolAddress((void**)&woutT, g_woutT);

    cudaFuncSetAttribute(gemm_tc<true>,
                         cudaFuncAttributeMaxDynamicSharedMemorySize, GEMM_SMEM);
    cudaFuncSetAttribute(gemm_tc<false>,
                         cudaFuncAttributeMaxDynamicSharedMemorySize, GEMM_SMEM);
    cudaFuncSetAttribute(attn_tc,
                         cudaFuncAttributeMaxDynamicSharedMemorySize, ATTN_SMEM);

    // tf32-round x; transpose + tf32-round weights
    cvt_tf32_k<<<(M_TOT * D_MODEL) / (256 * 4), 256>>>(x, xtf);
    transpose_k<<<dim3((3 * D_MODEL) / 32, D_MODEL / 32), dim3(32, 8)>>>(
        Wqkv, wqkvT, D_MODEL, 3 * D_MODEL);
    transpose_k<<<dim3(D_MODEL / 32, D_MODEL / 32), dim3(32, 8)>>>(
        Wout, woutT, D_MODEL, D_MODEL);

    // GEMM1: qkv = tf32(x @ Wqkv + b)
    gemm_tc<true><<<dim3((3 * D_MODEL) / 128, M_TOT / 128), 256, GEMM_SMEM>>>(
        xtf, wqkvT, bqkv, qkv, 3 * D_MODEL, D_MODEL);

    // Attention on tensor cores
    attn_tc<<<dim3(SEQ / 128, NH, BATCH), 256, ATTN_SMEM>>>(qkv, attn);

    // GEMM2: out = attn @ Wout + b (fp32 output)
    gemm_tc<false><<<dim3(D_MODEL / 128, M_TOT / 128), 256, GEMM_SMEM>>>(
        attn, woutT, bout, out, D_MODEL, D_MODEL);
}

// round 14
// speedup vs baseline: 4.7502x; 1.0488x over previous
#include <cuda_runtime.h>
#include <cstdint>

#define D_MODEL 1024
#define SEQ     2048
#define BATCH   2
#define NH      16
#define DH      64
#define M_TOT   (BATCH * SEQ)   // 4096 rows

// Scratch (allocation-free rule: __device__ globals)
__device__ float g_qkv  [(size_t)M_TOT * 3 * D_MODEL];     // [4096, 3072] tf32-rounded
__device__ float g_attn [(size_t)M_TOT * D_MODEL];         // [4096, 1024] tf32-rounded
__device__ float g_wqkvT[(size_t)3 * D_MODEL * D_MODEL];   // [3072, 1024] tf32
__device__ float g_woutT[(size_t)D_MODEL * D_MODEL];       // [1024, 1024] tf32

// ===========================================================================
// Helpers
// ===========================================================================
__device__ __forceinline__ uint32_t smem_u32(const void* p) {
    uint32_t a;
    asm("{ .reg .u64 t; cvta.to.shared.u64 t, %1; cvt.u32.u64 %0, t; }"
        : "=r"(a) : "l"(p));
    return a;
}
__device__ __forceinline__ float to_tf32(float x) {
    uint32_t u;
    asm("cvt.rna.tf32.f32 %0, %1;" : "=r"(u) : "f"(x));
    return __uint_as_float(u);
}
__device__ __forceinline__ uint32_t tf32bits(float x) {
    uint32_t u;
    asm("cvt.rna.tf32.f32 %0, %1;" : "=r"(u) : "f"(x));
    return u;
}
__device__ __forceinline__ float ex2f(float x) {
    float r;
    asm("ex2.approx.f32 %0, %1;" : "=f"(r) : "f"(x));
    return r;
}

#define CP_ASYNC16(saddr, gptr) \
    asm volatile("cp.async.cg.shared.global [%0], [%1], 16;" \
                 :: "r"(saddr), "l"(gptr) : "memory")
#define CP_COMMIT() asm volatile("cp.async.commit_group;" ::: "memory")

// D(16x8) += A(16x8, row) * B(8x8, col)  tf32 inputs, fp32 accumulate
#define MMA_TF32(c, a, b) \
    asm volatile("mma.sync.aligned.m16n8k8.row.col.f32.tf32.tf32.f32 " \
        "{%0,%1,%2,%3}, {%4,%5,%6,%7}, {%8,%9}, {%0,%1,%2,%3};" \
        : "+f"((c)[0]), "+f"((c)[1]), "+f"((c)[2]), "+f"((c)[3]) \
        : "r"((a)[0]), "r"((a)[1]), "r"((a)[2]), "r"((a)[3]), \
          "r"((b)[0]), "r"((b)[1]))

// ldmatrix x4: on 32-bit data, matrix j gives thread l the element at
// (row l/4, col l%4) of an 8x4 fp32 tile whose 8 row addresses come from
// lanes 8j..8j+7.
#define LDSM4(r0, r1, r2, r3, addr) \
    asm volatile("ldmatrix.sync.aligned.m8n8.x4.shared.b16 {%0,%1,%2,%3}, [%4];" \
        : "=r"(r0), "=r"(r1), "=r"(r2), "=r"(r3) : "r"(addr))

// ===========================================================================
// Transpose + tf32 round: out[C,R] = tf32(in[R,C]^T)
// ===========================================================================
__global__ void transpose_k(const float* __restrict__ in, float* __restrict__ out,
                            int R, int C)
{
    __shared__ float t[32][33];
    int tx = threadIdx.x, ty = threadIdx.y;
    int c0 = blockIdx.x * 32, r0 = blockIdx.y * 32;
    #pragma unroll
    for (int j = 0; j < 4; j++)
        t[ty + 8 * j][tx] = in[(size_t)(r0 + ty + 8 * j) * C + c0 + tx];
    __syncthreads();
    #pragma unroll
    for (int j = 0; j < 4; j++)
        out[(size_t)(c0 + ty + 8 * j) * R + r0 + tx] = to_tf32(t[tx][ty + 8 * j]);
}

// ===========================================================================
// mma.sync tf32 GEMM + bias: C[M,N] = A[M,K] @ Bt[N,K]^T + bias[N]
// 128x128 CTA, 8 warps (4Mx2N), warp tile 32x64, m16n8k8.
// Fragments via ldmatrix.x4 (rows at stride 36 -> phase banks 4r+c: clean).
// RNDOUT: tf32-round the stored output. RNDA: rna-round A fragments in
// register (lets GEMM1 consume raw fp32 x with identical numerics).
// ===========================================================================
#define KS       32
#define ASTRIDE  36
#define AROWB    (ASTRIDE * 4)
#define TILE_F   (128 * ASTRIDE)
#define TILE_BB  (TILE_F * 4)
#define STAGE_B  (2 * TILE_BB)
#define GEMM_SMEM (2 * STAGE_B)           // 73728 B

__device__ __forceinline__ void stage_load(uint32_t sA, uint32_t sB,
                                           const float* ga, const float* gb, int K)
{
    #pragma unroll
    for (int it = 0; it < 4; it++) {
        CP_ASYNC16(sA + it * 32 * AROWB, ga + (size_t)(32 * it) * K);
        CP_ASYNC16(sB + it * 32 * AROWB, gb + (size_t)(32 * it) * K);
    }
    CP_COMMIT();
}

template<bool RNDOUT, bool RNDA>
__global__ __launch_bounds__(256, 2) void gemm_tc(
    const float* __restrict__ A, const float* __restrict__ Bt,
    const float* __restrict__ bias, float* __restrict__ C,
    int N, int K)
{
    extern __shared__ float smf[];
    const uint32_t sbase = smem_u32(smf);

    const int tid  = threadIdx.x;
    const int wid  = tid >> 5;
    const int lane = tid & 31;
    const int grp  = lane >> 2;
    const int qd   = lane & 3;
    const int wm   = wid & 3;
    const int wn   = wid >> 2;
    const int m0   = blockIdx.y * 128;
    const int n0   = blockIdx.x * 128;

    // ldmatrix per-lane address offsets (bytes). mi = matrix index 0..3.
    const int mi = lane >> 3;
    const int r8 = lane & 7;
    uint32_t aOff[2], bOff[4];
    #pragma unroll
    for (int mb = 0; mb < 2; mb++)
        aOff[mb] = ((wm * 32 + mb * 16 + (mi & 1) * 8 + r8) * ASTRIDE
                    + (mi >> 1) * 4) * 4;
    #pragma unroll
    for (int p = 0; p < 4; p++)
        bOff[p] = ((wn * 64 + (2 * p + (mi >> 1)) * 8 + r8) * ASTRIDE
                   + (mi & 1) * 4) * 4 + TILE_BB;

    const float* Ag = A  + (size_t)(m0 + (tid >> 3)) * K + (tid & 7) * 4;
    const float* Bg = Bt + (size_t)(n0 + (tid >> 3)) * K + (tid & 7) * 4;
    const uint32_t dA = sbase + (tid >> 3) * AROWB + (tid & 7) * 16;
    const uint32_t dB = dA + TILE_BB;

    const int NS = K / KS;

    float acc[2][8][4] = {};

    stage_load(dA, dB, Ag, Bg, K);
    stage_load(dA + STAGE_B, dB + STAGE_B, Ag + KS, Bg + KS, K);

    for (int s = 0; s < NS; s++) {
        if (s + 1 < NS) asm volatile("cp.async.wait_group 1;" ::: "memory");
        else            asm volatile("cp.async.wait_group 0;" ::: "memory");
        __syncthreads();

        const uint32_t sb = sbase + (s & 1) * STAGE_B;

        #pragma unroll
        for (int ks = 0; ks < 4; ks++) {
            uint32_t a[2][4], b[8][2];
            #pragma unroll
            for (int mb = 0; mb < 2; mb++) {
                LDSM4(a[mb][0], a[mb][1], a[mb][2], a[mb][3],
                      sb + aOff[mb] + ks * 32);
                if (RNDA) {
                    #pragma unroll
                    for (int j = 0; j < 4; j++)
                        a[mb][j] = tf32bits(__uint_as_float(a[mb][j]));
                }
            }
            #pragma unroll
            for (int p = 0; p < 4; p++)
                LDSM4(b[2 * p][0], b[2 * p][1], b[2 * p + 1][0], b[2 * p + 1][1],
                      sb + bOff[p] + ks * 32);
            #pragma unroll
            for (int mb = 0; mb < 2; mb++)
                #pragma unroll
                for (int nb = 0; nb < 8; nb++)
                    MMA_TF32(acc[mb][nb], a[mb], b[nb]);
        }
        __syncthreads();
        if (s + 2 < NS)
            stage_load(dA + ((s + 2) & 1) * STAGE_B, dB + ((s + 2) & 1) * STAGE_B,
                       Ag + (size_t)(s + 2) * KS, Bg + (size_t)(s + 2) * KS, K);
    }

    const float* brow = bias + n0 + wn * 64;
    #pragma unroll
    for (int mb = 0; mb < 2; mb++) {
        #pragma unroll
        for (int half = 0; half < 2; half++) {
            const int row = m0 + wm * 32 + mb * 16 + grp + half * 8;
            float* crow = C + (size_t)row * N + n0 + wn * 64;
            #pragma unroll
            for (int nb = 0; nb < 8; nb++) {
                float2 bb = *(const float2*)(brow + nb * 8 + 2 * qd);
                float2 o;
                o.x = acc[mb][nb][half * 2 + 0] + bb.x;
                o.y = acc[mb][nb][half * 2 + 1] + bb.y;
                if (RNDOUT) { o.x = to_tf32(o.x); o.y = to_tf32(o.y); }
                *(float2*)(crow + nb * 8 + 2 * qd) = o;
            }
        }
    }
}

// ===========================================================================
// Flash attention on mma.sync tf32 (R13 kernel + ldmatrix Q/K fragments).
// CTA = 128 queries of one (b,h); 8 warps, each owns a 16-query m16 strip.
// Qs [128][68], Ks [2][64][68] (ldmatrix: stride 68 = 4 mod 32, clean),
// Vs [2][64][72] (scalar B-frag LDS, bank 8qd+grp: clean).
// 106496 B dynamic smem -> 2 CTAs/SM.
// ===========================================================================
#define ATTN_SMEM 106496

__global__ __launch_bounds__(256, 2) void attn_tc(
    const float* __restrict__ qkv,   // [M_TOT, 3*D_MODEL] tf32-rounded
    float* __restrict__ out)         // [M_TOT, D_MODEL]
{
    extern __shared__ float sm[];
    float* Vs = sm + 17408;

    const uint32_t sbase = smem_u32(sm);
    const uint32_t KsU = sbase + 8704u * 4u;
    const uint32_t VsU = sbase + 17408u * 4u;

    const int tid  = threadIdx.x;
    const int wid  = tid >> 5;
    const int lane = tid & 31;
    const int grp  = lane >> 2;
    const int qd   = lane & 3;
    const int q0   = blockIdx.x * 128;
    const int hoff = blockIdx.y * DH;
    const int bT   = blockIdx.z * SEQ;

    const int lrow = tid >> 4;        // 0..15
    const int lch  = tid & 15;        // 16B chunk within 64-float row

    // ldmatrix per-lane addresses
    const int mi = lane >> 3;
    const int r8 = lane & 7;
    const uint32_t qAddr = sbase + ((16 * wid + (mi & 1) * 8 + r8) * 68
                                    + (mi >> 1) * 4) * 4;
    uint32_t kOff[4];
    #pragma unroll
    for (int p = 0; p < 4; p++)
        kOff[p] = (((2 * p + (mi >> 1)) * 8 + r8) * 68 + (mi & 1) * 4) * 4;

    // ---- stage K/V tile (64 keys) into buffer p ----
    auto stage_kv = [&](int p, int k0) {
        const float* kg = qkv + (size_t)(bT + k0 + lrow) * 3072 + 1024 + hoff + lch * 4;
        uint32_t dk = KsU + (uint32_t)p * 17408u + lrow * 272u + lch * 16u;
        uint32_t dv = VsU + (uint32_t)p * 18432u + lrow * 288u + lch * 16u;
        #pragma unroll
        for (int it = 0; it < 4; it++) {
            CP_ASYNC16(dk + it * 16 * 272, kg + (size_t)it * 16 * 3072);
            CP_ASYNC16(dv + it * 16 * 288, kg + 1024 + (size_t)it * 16 * 3072);
        }
        CP_COMMIT();
    };

    stage_kv(0, 0);
    stage_kv(1, 64);

    // ---- load Q tile (128 x 64) ----
    #pragma unroll
    for (int it = 0; it < 8; it++) {
        int row = lrow + 16 * it;
        float4 v = *(const float4*)(qkv + (size_t)(bT + q0 + row) * 3072 + hoff + lch * 4);
        *(float4*)(&sm[row * 68 + lch * 4]) = v;
    }

    float m0 = -1e30f, m1 = -1e30f, l0 = 0.f, l1 = 0.f;
    float o[8][4] = {};

    const int src_lo = (lane & 28) | (qd >> 1);
    const int src_hi = src_lo + 2;
    const bool odd = qd & 1;

    for (int kt = 0; kt < SEQ / 64; kt++) {
        const int p = kt & 1;
        if (kt + 1 < SEQ / 64) asm volatile("cp.async.wait_group 1;" ::: "memory");
        else                   asm volatile("cp.async.wait_group 0;" ::: "memory");
        __syncthreads();

        const uint32_t kbuf = KsU + (uint32_t)p * 17408u;
        const float* vp = Vs + p * 4608 + qd * 72 + grp;

        // ---- S = Q K^T : 64 mma, fragments via ldmatrix ----
        float s[8][4] = {};
        #pragma unroll
        for (int kb = 0; kb < 8; kb++) {
            uint32_t a[4], b[8][2];
            LDSM4(a[0], a[1], a[2], a[3], qAddr + kb * 32);
            #pragma unroll
            for (int pp = 0; pp < 4; pp++)
                LDSM4(b[2 * pp][0], b[2 * pp][1], b[2 * pp + 1][0], b[2 * pp + 1][1],
                      kbuf + kOff[pp] + kb * 32);
            #pragma unroll
            for (int nb = 0; nb < 8; nb++)
                MMA_TF32(s[nb], a, b[nb]);
        }

        // ---- online softmax (base-2; rows grp / grp+8 live in quads) ----
        const float c1 = 0.18033688011112042f;   // (1/8) * log2(e)
        float t0 = -1e30f, t1 = -1e30f;
        #pragma unroll
        for (int nb = 0; nb < 8; nb++) {
            s[nb][0] *= c1; s[nb][1] *= c1; s[nb][2] *= c1; s[nb][3] *= c1;
            t0 = fmaxf(t0, fmaxf(s[nb][0], s[nb][1]));
            t1 = fmaxf(t1, fmaxf(s[nb][2], s[nb][3]));
        }
        t0 = fmaxf(t0, __shfl_xor_sync(0xffffffffu, t0, 1));
        t0 = fmaxf(t0, __shfl_xor_sync(0xffffffffu, t0, 2));
        t1 = fmaxf(t1, __shfl_xor_sync(0xffffffffu, t1, 1));
        t1 = fmaxf(t1, __shfl_xor_sync(0xffffffffu, t1, 2));

        float mn0 = fmaxf(m0, t0), mn1 = fmaxf(m1, t1);
        float al0 = ex2f(m0 - mn0), al1 = ex2f(m1 - mn1);
        m0 = mn0; m1 = mn1;

        float rs0 = 0.f, rs1 = 0.f;
        #pragma unroll
        for (int nb = 0; nb < 8; nb++) {
            s[nb][0] = ex2f(s[nb][0] - mn0);
            s[nb][1] = ex2f(s[nb][1] - mn0);
            s[nb][2] = ex2f(s[nb][2] - mn1);
            s[nb][3] = ex2f(s[nb][3] - mn1);
            rs0 += s[nb][0] + s[nb][1];
            rs1 += s[nb][2] + s[nb][3];
        }
        rs0 += __shfl_xor_sync(0xffffffffu, rs0, 1);
        rs0 += __shfl_xor_sync(0xffffffffu, rs0, 2);
        rs1 += __shfl_xor_sync(0xffffffffu, rs1, 1);
        rs1 += __shfl_xor_sync(0xffffffffu, rs1, 2);
        l0 = l0 * al0 + rs0;
        l1 = l1 * al1 + rs1;

        #pragma unroll
        for (int nb = 0; nb < 8; nb++) {
            o[nb][0] *= al0; o[nb][1] *= al0;
            o[nb][2] *= al1; o[nb][3] *= al1;
        }

        // ---- O += P V : convert P C-frag -> A-frag via quad shuffles ----
        #pragma unroll
        for (int kb = 0; kb < 8; kb++) {
            float x0 = __shfl_sync(0xffffffffu, s[kb][0], src_lo);
            float x1 = __shfl_sync(0xffffffffu, s[kb][1], src_lo);
            float y0 = __shfl_sync(0xffffffffu, s[kb][0], src_hi);
            float y1 = __shfl_sync(0xffffffffu, s[kb][1], src_hi);
            float z0 = __shfl_sync(0xffffffffu, s[kb][2], src_lo);
            float z1 = __shfl_sync(0xffffffffu, s[kb][3], src_lo);
            float w0 = __shfl_sync(0xffffffffu, s[kb][2], src_hi);
            float w1 = __shfl_sync(0xffffffffu, s[kb][3], src_hi);
            uint32_t a[4];
            a[0] = tf32bits(odd ? x1 : x0);
            a[1] = tf32bits(odd ? z1 : z0);
            a[2] = tf32bits(odd ? y1 : y0);
            a[3] = tf32bits(odd ? w1 : w0);
            const float* vpp = vp + kb * 576;
            #pragma unroll
            for (int nb = 0; nb < 8; nb++) {
                uint32_t b[2];
                b[0] = __float_as_uint(vpp[nb * 8]);
                b[1] = __float_as_uint(vpp[nb * 8 + 288]);
                MMA_TF32(o[nb], a, b);
            }
        }

        __syncthreads();
        if (kt + 2 < SEQ / 64) stage_kv(p, (kt + 2) * 64);
    }

    // ---- normalize + tf32-round (GEMM2 input) + store ----
    const float inv0 = 1.0f / l0, inv1 = 1.0f / l1;
    const int r0 = bT + q0 + 16 * wid + grp;
    float* p0 = out + (size_t)r0 * D_MODEL + hoff + 2 * qd;
    float* p1 = p0 + (size_t)8 * D_MODEL;
    #pragma unroll
    for (int nb = 0; nb < 8; nb++) {
        float2 lo, hi;
        lo.x = to_tf32(o[nb][0] * inv0); lo.y = to_tf32(o[nb][1] * inv0);
        hi.x = to_tf32(o[nb][2] * inv1); hi.y = to_tf32(o[nb][3] * inv1);
        *(float2*)(p0 + 8 * nb) = lo;
        *(float2*)(p1 + 8 * nb) = hi;
    }
}

// ===========================================================================
// Launch
// ===========================================================================
extern "C" void kernel_launch(void* const* d_in, const int* in_sizes, int n_in,
                              void* d_out, int out_size)
{
    (void)in_sizes; (void)n_in; (void)out_size;
    const float* x    = (const float*)d_in[0];
    const float* Wqkv = (const float*)d_in[1];
    const float* bqkv = (const float*)d_in[2];
    const float* Wout = (const float*)d_in[3];
    const float* bout = (const float*)d_in[4];
    float* out = (float*)d_out;

    float *qkv, *attn, *wqkvT, *woutT;
    cudaGetSymbolAddress((void**)&qkv,   g_qkv);
    cudaGetSymbolAddress((void**)&attn,  g_attn);
    cudaGetSymbolAddress((void**)&wqkvT, g_wqkvT);
    cudaGetSymbolAddress((void**)&woutT, g_woutT);

    cudaFuncSetAttribute((const void*)gemm_tc<true, true>,
                         cudaFuncAttributeMaxDynamicSharedMemorySize, GEMM_SMEM);
    cudaFuncSetAttribute((const void*)gemm_tc<false, false>,
                         cudaFuncAttributeMaxDynamicSharedMemorySize, GEMM_SMEM);
    cudaFuncSetAttribute((const void*)attn_tc,
                         cudaFuncAttributeMaxDynamicSharedMemorySize, ATTN_SMEM);

    // transpose + tf32-round weights
    transpose_k<<<dim3((3 * D_MODEL) / 32, D_MODEL / 32), dim3(32, 8)>>>(
        Wqkv, wqkvT, D_MODEL, 3 * D_MODEL);
    transpose_k<<<dim3(D_MODEL / 32, D_MODEL / 32), dim3(32, 8)>>>(
        Wout, woutT, D_MODEL, D_MODEL);

    // GEMM1: qkv = tf32(x @ Wqkv + b)  (A rna-rounded in-register)
    gemm_tc<true, true><<<dim3((3 * D_MODEL) / 128, M_TOT / 128), 256, GEMM_SMEM>>>(
        x, wqkvT, bqkv, qkv, 3 * D_MODEL, D_MODEL);

    // Attention on tensor cores
    attn_tc<<<dim3(SEQ / 128, NH, BATCH), 256, ATTN_SMEM>>>(qkv, attn);

    // GEMM2: out = attn @ Wout + b (fp32 output)
    gemm_tc<false, false><<<dim3(D_MODEL / 128, M_TOT / 128), 256, GEMM_SMEM>>>(
        attn, woutT, bout, out, D_MODEL, D_MODEL);
}